// round 1
// baseline (speedup 1.0000x reference)
#include <cuda_runtime.h>

// Problem constants
#define NPTS   16384
#define NCHAN  64
#define DX     100
#define DY     88
#define DZ     80
#define PLANE  (DX*DY*DZ)          // 704000 elements per channel
#define WARPS_PER_BLOCK 8
#define NBLOCKS (NPTS / WARPS_PER_BLOCK)   // 2048

// Deterministic two-stage reduction scratch (no atomics).
__device__ float g_partials[NBLOCKS];

__device__ __forceinline__ int redirect(int v, int idx0, int m) {
    int r = (v - idx0) % m;
    return (r < 0) ? r + m : r;
}

__global__ void __launch_bounds__(256)
ccl_gather_kernel(const float* __restrict__ fixf,
                  const float* __restrict__ movf,
                  const int*   __restrict__ fp,
                  const int*   __restrict__ pp,
                  const int*   __restrict__ np_)
{
    const int warp = threadIdx.x >> 5;
    const int lane = threadIdx.x & 31;
    const int b    = blockIdx.x * WARPS_PER_BLOCK + warp;   // one point per warp

    // Redirected linear voxel index per point (uniform across warp -> broadcast loads)
    const int fx = redirect(fp[b*3+0],  25, DX);
    const int fy = redirect(fp[b*3+1], 225, DY);
    const int fz = redirect(fp[b*3+2],  28, DZ);
    const int px = redirect(pp[b*3+0],  25, DX);
    const int py = redirect(pp[b*3+1], 225, DY);
    const int pz = redirect(pp[b*3+2],  28, DZ);
    const int nx = redirect(np_[b*3+0],  25, DX);
    const int ny = redirect(np_[b*3+1], 225, DY);
    const int nz = redirect(np_[b*3+2],  28, DZ);

    const int fidx = fx*(DY*DZ) + fy*DZ + fz;
    const int pidx = px*(DY*DZ) + py*DZ + pz;
    const int nidx = nx*(DY*DZ) + ny*DZ + nz;

    const float* __restrict__ pf = fixf + fidx;
    const float* __restrict__ pq = movf + pidx;
    const float* __restrict__ pn = movf + nidx;

    // Lane l handles channels l and l+32: 6 independent random loads per lane.
    float dpos = 0.0f, dneg = 0.0f;
#pragma unroll
    for (int i = 0; i < 2; i++) {
        const int c = lane + i*32;
        const float f = __ldg(pf + c*PLANE);
        const float p = __ldg(pq + c*PLANE);
        const float n = __ldg(pn + c*PLANE);
        const float dp = f - p;
        const float dn = f - n;
        dpos = fmaf(dp, dp, dpos);
        dneg = fmaf(dn, dn, dneg);
    }

    // Warp reduce both distances
#pragma unroll
    for (int off = 16; off > 0; off >>= 1) {
        dpos += __shfl_xor_sync(0xffffffffu, dpos, off);
        dneg += __shfl_xor_sync(0xffffffffu, dneg, off);
    }

    __shared__ float s_loss[WARPS_PER_BLOCK];
    if (lane == 0) {
        const float loss_pos = dpos * dpos;
        float t = 1.0f - sqrtf(dneg);           // MARGIN = 1.0
        t = fmaxf(t, 0.0f);
        const float loss_neg = t * t;
        s_loss[warp] = loss_pos + loss_neg;
    }
    __syncthreads();

    if (threadIdx.x == 0) {
        float acc = 0.0f;
#pragma unroll
        for (int i = 0; i < WARPS_PER_BLOCK; i++) acc += s_loss[i];
        g_partials[blockIdx.x] = acc;
    }
}

__global__ void __launch_bounds__(1024)
ccl_reduce_kernel(float* __restrict__ out)
{
    __shared__ float s[1024];
    // NBLOCKS = 2048 partials, 1024 threads: each loads 2.
    float v = g_partials[threadIdx.x] + g_partials[threadIdx.x + 1024];
    s[threadIdx.x] = v;
    __syncthreads();
#pragma unroll
    for (int off = 512; off > 0; off >>= 1) {
        if (threadIdx.x < off) s[threadIdx.x] += s[threadIdx.x + off];
        __syncthreads();
    }
    if (threadIdx.x == 0) {
        // loss = sum / (2 * 2B) * 1e6  = sum * (1e6 / 65536)
        out[0] = s[0] * (1000000.0f / (4.0f * (float)NPTS));
    }
}

extern "C" void kernel_launch(void* const* d_in, const int* in_sizes, int n_in,
                              void* d_out, int out_size)
{
    const float* fixf = (const float*)d_in[0];
    const float* movf = (const float*)d_in[1];
    const int*   fp   = (const int*)d_in[2];
    const int*   pp   = (const int*)d_in[3];
    const int*   np_  = (const int*)d_in[4];
    float* out = (float*)d_out;

    ccl_gather_kernel<<<NBLOCKS, 256>>>(fixf, movf, fp, pp, np_);
    ccl_reduce_kernel<<<1, 1024>>>(out);
}